// round 4
// baseline (speedup 1.0000x reference)
#include <cuda_runtime.h>
#include <cstdint>

#define DEV_INLINE __device__ __forceinline__

// Problem constants
constexpr int Bn = 64, Sn = 196, En = 512, Hn = 512, An = 256, Dn = 512,
              Vn = 32000, Ln = 32, Tn = 31;
constexpr int KX = 1536;   // xcat row: [embedded(512) | context(512) | h(512)]
constexpr int NG = 2048;   // GRU gemm N: [r(512) z(512) gi_n(512) gh_n(512)]
constexpr int SPLITK = 4;

// Scratch (device globals — no allocations allowed). 16B-aligned for float4.
__device__ __align__(16) float g_enc_proj[Bn * Sn * An];  // 12.8 MB
__device__ __align__(16) float g_h_all[2048 * Hn];        // rows t*64+b = h_{t+1}[b]
__device__ __align__(16) float g_xcat[Bn * KX];
__device__ __align__(16) float g_gpart[SPLITK * Bn * NG];
__device__ __align__(16) float g_h[Bn * Hn];
__device__ __align__(16) float g_decproj[Bn * An];        // dec_proj(h_t) + b_dec
__device__ __align__(16) float g_Wcat[NG * KX];           // packed [W_ih | W_hh]
__device__ __align__(16) float g_bcat[NG];
__device__ int g_tok_is_i64;                              // targets dtype flag

DEV_INLINE unsigned f2tf32(float f) {
    unsigned u; asm("cvt.rna.tf32.f32 %0, %1;" : "=r"(u) : "f"(f)); return u;
}
DEV_INLINE float tanh_fast(float x) {
    float y; asm("tanh.approx.f32 %0, %1;" : "=f"(y) : "f"(x)); return y;
}
DEV_INLINE void mma8(float c[4], const unsigned a[4], const unsigned b[2]) {
    asm volatile(
        "mma.sync.aligned.m16n8k8.row.col.f32.tf32.tf32.f32 "
        "{%0,%1,%2,%3}, {%4,%5,%6,%7}, {%8,%9}, {%0,%1,%2,%3};"
        : "+f"(c[0]), "+f"(c[1]), "+f"(c[2]), "+f"(c[3])
        : "r"(a[0]), "r"(a[1]), "r"(a[2]), "r"(a[3]), "r"(b[0]), "r"(b[1]));
}

// ---------------------------------------------------------------------------
// targets dtype probe, BOUNDED to first 1024 tokens so max word index read is
// 2047 — in-bounds whether the 2048-element buffer is int32 (2048 words) or
// int64 (4096 words). If all odd words are 0 -> int64 layout (high words of
// small tokens); else int32. Deterministic.
// ---------------------------------------------------------------------------
__global__ void detect_tok_dtype(const int* __restrict__ traw)
{
    __shared__ int any;
    if (threadIdx.x == 0) any = 0;
    __syncthreads();
    for (int i = threadIdx.x; i < (Bn * Ln) / 2; i += blockDim.x)
        if (traw[2 * i + 1] != 0) any = 1;
    __syncthreads();
    if (threadIdx.x == 0) g_tok_is_i64 = (any == 0) ? 1 : 0;
}

// ---------------------------------------------------------------------------
// Generic tf32 GEMM:  C[m,n] = sum_k A[m,K] * B[n,K]   (both K-major)
// MODE 0: C = acc + bias (row-major, ld=N), guard m<M
// MODE 1: split-K partial store to C + blockIdx.z*M*N (no bias)
// MODE 2: logits store: row m -> (t = m/64, b = m%64), out[(b*31+t)*N + n] + bias
// ---------------------------------------------------------------------------
template <int BM, int BN, int MODE>
__global__ __launch_bounds__(256) void gemm_tf32(
    const float* __restrict__ A, const float* __restrict__ B,
    float* __restrict__ C, const float* __restrict__ bias,
    int M, int N, int K)
{
    constexpr int BK = 16;
    __shared__ unsigned As[BM][BK + 1];
    __shared__ unsigned Bs[BN][BK + 1];

    const int tid = threadIdx.x;
    const int lane = tid & 31;
    const int wid = tid >> 5;
    const int grp = lane >> 2;
    const int tig = lane & 3;

    constexpr int NWN = 4;                 // warps: 2 (m) x 4 (n)
    const int wm = wid / NWN;              // 0..1
    const int wn = wid % NWN;              // 0..3
    constexpr int WTM = BM / 2;            // warp tile rows
    constexpr int WTN = BN / 4;            // warp tile cols (32)
    constexpr int MI = WTM / 16;
    constexpr int NI = WTN / 8;

    int mblk, nblk;
    if (MODE == 2) { mblk = blockIdx.x; nblk = blockIdx.y; }
    else           { mblk = blockIdx.y; nblk = blockIdx.x; }

    const int kchunk = K / gridDim.z;
    const int kbase  = blockIdx.z * kchunk;
    const int kIters = kchunk / BK;

    const int lr = tid >> 2;               // 0..63
    const int lc = (tid & 3) * 4;          // 0,4,8,12
    constexpr int LA = BM / 64;
    constexpr int LB = BN / 64;

    float4 aReg[LA], bReg[LB];
    auto loadTile = [&](int kt) {
        const int kg = kbase + kt * BK + lc;
#pragma unroll
        for (int i = 0; i < LA; i++) {
            int gr = mblk * BM + lr + i * 64;
            if (gr >= M) gr = M - 1;
            aReg[i] = *reinterpret_cast<const float4*>(A + (size_t)gr * K + kg);
        }
#pragma unroll
        for (int i = 0; i < LB; i++) {
            int gr = nblk * BN + lr + i * 64;
            bReg[i] = *reinterpret_cast<const float4*>(B + (size_t)gr * K + kg);
        }
    };

    float acc[MI][NI][4];
#pragma unroll
    for (int mi = 0; mi < MI; mi++)
#pragma unroll
        for (int ni = 0; ni < NI; ni++)
#pragma unroll
            for (int q = 0; q < 4; q++) acc[mi][ni][q] = 0.f;

    loadTile(0);
    for (int kt = 0; kt < kIters; kt++) {
        __syncthreads();
#pragma unroll
        for (int i = 0; i < LA; i++) {
            As[lr + i * 64][lc + 0] = f2tf32(aReg[i].x);
            As[lr + i * 64][lc + 1] = f2tf32(aReg[i].y);
            As[lr + i * 64][lc + 2] = f2tf32(aReg[i].z);
            As[lr + i * 64][lc + 3] = f2tf32(aReg[i].w);
        }
#pragma unroll
        for (int i = 0; i < LB; i++) {
            Bs[lr + i * 64][lc + 0] = f2tf32(bReg[i].x);
            Bs[lr + i * 64][lc + 1] = f2tf32(bReg[i].y);
            Bs[lr + i * 64][lc + 2] = f2tf32(bReg[i].z);
            Bs[lr + i * 64][lc + 3] = f2tf32(bReg[i].w);
        }
        __syncthreads();
        if (kt + 1 < kIters) loadTile(kt + 1);   // overlap gmem with compute

#pragma unroll
        for (int ks = 0; ks < 2; ks++) {
            const int k0 = ks * 8;
            unsigned af[MI][4];
#pragma unroll
            for (int mi = 0; mi < MI; mi++) {
                const int r = wm * WTM + mi * 16 + grp;
                af[mi][0] = As[r][k0 + tig];
                af[mi][1] = As[r + 8][k0 + tig];
                af[mi][2] = As[r][k0 + tig + 4];
                af[mi][3] = As[r + 8][k0 + tig + 4];
            }
            unsigned bf[NI][2];
#pragma unroll
            for (int ni = 0; ni < NI; ni++) {
                const int c = wn * WTN + ni * 8 + grp;
                bf[ni][0] = Bs[c][k0 + tig];
                bf[ni][1] = Bs[c][k0 + tig + 4];
            }
#pragma unroll
            for (int mi = 0; mi < MI; mi++)
#pragma unroll
                for (int ni = 0; ni < NI; ni++)
                    mma8(acc[mi][ni], af[mi], bf[ni]);
        }
    }

    float* Cp = C;
    if (MODE == 1) Cp = C + (size_t)blockIdx.z * M * N;
#pragma unroll
    for (int mi = 0; mi < MI; mi++) {
#pragma unroll
        for (int ni = 0; ni < NI; ni++) {
            const int r0 = mblk * BM + wm * WTM + mi * 16 + grp;
            const int c0 = nblk * BN + wn * WTN + ni * 8 + tig * 2;
#pragma unroll
            for (int hh = 0; hh < 2; hh++) {
                const int r = r0 + hh * 8;
                const float v0 = acc[mi][ni][hh * 2 + 0];
                const float v1 = acc[mi][ni][hh * 2 + 1];
                if (MODE == 0) {
                    if (r < M) {
                        Cp[(size_t)r * N + c0]     = v0 + bias[c0];
                        Cp[(size_t)r * N + c0 + 1] = v1 + bias[c0 + 1];
                    }
                } else if (MODE == 1) {
                    Cp[(size_t)r * N + c0]     = v0;
                    Cp[(size_t)r * N + c0 + 1] = v1;
                } else {
                    if (r < M) {
                        const int tt = r >> 6, bb = r & 63;
                        const size_t o = ((size_t)bb * Tn + tt) * (size_t)N + c0;
                        Cp[o]     = v0 + bias[c0];
                        Cp[o + 1] = v1 + bias[c0 + 1];
                    }
                }
            }
        }
    }
}

// ---------------------------------------------------------------------------
// Weight packing (runs every launch; idempotent/deterministic)
// Wcat[j][k], K = [x(1024) | h(512)]:
//   j <1024 (r,z):     [W_ih[j] | W_hh[j]]
//   1024..1535 (gi_n): [W_ih[j] | 0]
//   1536..2047 (gh_n): [0 | W_hh[j-512]]
// ---------------------------------------------------------------------------
__global__ void pack_wcat(const float* __restrict__ W_ih,
                          const float* __restrict__ W_hh)
{
    const int idx = blockIdx.x * blockDim.x + threadIdx.x;
    if (idx >= NG * KX) return;
    const int j = idx / KX, k = idx - j * KX;
    float v = 0.f;
    if (j < 1536) {
        if (k < 1024) v = W_ih[(size_t)j * 1024 + k];
        else if (j < 1024) v = W_hh[(size_t)j * 512 + (k - 1024)];
    } else {
        if (k >= 1024) v = W_hh[(size_t)(j - 512) * 512 + (k - 1024)];
    }
    g_Wcat[idx] = v;
}

__global__ void pack_bcat(const float* __restrict__ b_ih,
                          const float* __restrict__ b_hh)
{
    const int j = blockIdx.x * blockDim.x + threadIdx.x;
    if (j >= NG) return;
    float v;
    if (j < 1024)      v = b_ih[j] + b_hh[j];
    else if (j < 1536) v = b_ih[j];
    else               v = b_hh[j - 512];
    g_bcat[j] = v;
}

// ---------------------------------------------------------------------------
// Setup: h0 = tanh(pooled @ W_init.T + b_init); dec_proj(h0) + b_dec
// ---------------------------------------------------------------------------
__global__ void setup_h0(const float* __restrict__ pooled,
                         const float* __restrict__ W_init,
                         const float* __restrict__ b_init,
                         const float* __restrict__ W_dec,
                         const float* __restrict__ b_dec)
{
    __shared__ float h0s[Hn];
    const int b = blockIdx.x;
    const int tid = threadIdx.x, wid = tid >> 5, lane = tid & 31;
    const float* pb = pooled + (size_t)b * En;

    for (int j = wid; j < Hn; j += 8) {
        const float* wr = W_init + (size_t)j * En;
        float s = 0.f;
        for (int e = lane; e < En; e += 32) s += pb[e] * wr[e];
#pragma unroll
        for (int o = 16; o > 0; o >>= 1) s += __shfl_xor_sync(0xffffffffu, s, o);
        if (lane == 0) h0s[j] = tanhf(s + b_init[j]);
    }
    __syncthreads();
    for (int j = tid; j < Hn; j += blockDim.x) {
        const float v = h0s[j];
        g_h[b * Hn + j] = v;
        g_xcat[b * KX + 1024 + j] = v;
    }
    for (int a = wid; a < An; a += 8) {
        const float* wr = W_dec + (size_t)a * Hn;
        float s = 0.f;
        for (int e = lane; e < Hn; e += 32) s += h0s[e] * wr[e];
#pragma unroll
        for (int o = 16; o > 0; o >>= 1) s += __shfl_xor_sync(0xffffffffu, s, o);
        if (lane == 0) g_decproj[b * An + a] = s + b_dec[a];
    }
}

// ---------------------------------------------------------------------------
// Per-step attention: energy/softmax/context + embedding gather -> xcat
// ---------------------------------------------------------------------------
__global__ void attn_step(const float* __restrict__ enc,       // (B,S,E)
                          const float* __restrict__ W_score,   // (256)
                          const int* __restrict__ traw,
                          const float* __restrict__ emb, int t)
{
    __shared__ float dp[An];
    __shared__ float w[Sn];
    __shared__ float red[8];
    const int b = blockIdx.x;
    const int tid = threadIdx.x, wid = tid >> 5, lane = tid & 31;

    dp[tid] = g_decproj[b * An + tid];   // blockDim == An == 256

    {   // embedding lookup (padding_idx = 2 -> zeros); dtype-agnostic read
        const int i = b * Ln + t;
        int tok = g_tok_is_i64 ? traw[2 * i] : traw[i];
        if (tok < 0) tok = 0;
        if (tok >= Vn) tok = Vn - 1;       // safety clamp (never OOB)
        const float* er = emb + (size_t)tok * Dn;
        const bool pad = (tok == 2);
        for (int d = tid; d < Dn; d += blockDim.x)
            g_xcat[b * KX + d] = pad ? 0.f : er[d];
    }
    __syncthreads();

    // scores[s] = sum_a tanh(enc_proj + dec_proj) * W_score[a]
    const float* epb = g_enc_proj + (size_t)b * Sn * An;
    for (int s0 = wid; s0 < Sn; s0 += 8) {
        const float* er = epb + (size_t)s0 * An;
        float sc = 0.f;
#pragma unroll
        for (int a = lane; a < An; a += 32)
            sc += tanh_fast(er[a] + dp[a]) * W_score[a];
#pragma unroll
        for (int o = 16; o > 0; o >>= 1) sc += __shfl_xor_sync(0xffffffffu, sc, o);
        if (lane == 0) w[s0] = sc;
    }
    __syncthreads();

    // softmax over S (b_score shift is softmax-invariant -> skipped)
    const float v = (tid < Sn) ? w[tid] : -1e30f;
    float mx = v;
#pragma unroll
    for (int o = 16; o > 0; o >>= 1) mx = fmaxf(mx, __shfl_xor_sync(0xffffffffu, mx, o));
    if (lane == 0) red[wid] = mx;
    __syncthreads();
    float gmx = red[0];
#pragma unroll
    for (int i = 1; i < 8; i++) gmx = fmaxf(gmx, red[i]);
    __syncthreads();
    const float ev = (tid < Sn) ? __expf(v - gmx) : 0.f;
    float sm = ev;
#pragma unroll
    for (int o = 16; o > 0; o >>= 1) sm += __shfl_xor_sync(0xffffffffu, sm, o);
    if (lane == 0) red[wid] = sm;
    __syncthreads();
    float tot = 0.f;
#pragma unroll
    for (int i = 0; i < 8; i++) tot += red[i];
    if (tid < Sn) w[tid] = ev * (1.f / tot);
    __syncthreads();

    // context[e] = sum_s w[s] * enc[b,s,e]
    const float* eb = enc + (size_t)b * Sn * En;
    for (int e0 = tid; e0 < En; e0 += blockDim.x) {
        float acc = 0.f;
#pragma unroll 4
        for (int s = 0; s < Sn; s++) acc += w[s] * eb[(size_t)s * En + e0];
        g_xcat[b * KX + 512 + e0] = acc;
    }
}

// ---------------------------------------------------------------------------
// Gates: combine split-K partials + biases -> h_new; also dec_proj(h_new)
// ---------------------------------------------------------------------------
__global__ void gru_gates(const float* __restrict__ W_dec,
                          const float* __restrict__ b_dec, int t)
{
    __shared__ float hs[Hn];
    const int b = blockIdx.x;
    const int j = threadIdx.x;   // 512 threads == Hn

    float rp  = g_bcat[j];
    float zp  = g_bcat[512 + j];
    float gin = g_bcat[1024 + j];
    float ghn = g_bcat[1536 + j];
#pragma unroll
    for (int p = 0; p < SPLITK; p++) {
        const float* gp = g_gpart + (size_t)p * Bn * NG + (size_t)b * NG;
        rp  += gp[j];
        zp  += gp[512 + j];
        gin += gp[1024 + j];
        ghn += gp[1536 + j];
    }
    const float r = 1.f / (1.f + expf(-rp));
    const float z = 1.f / (1.f + expf(-zp));
    const float n = tanhf(gin + r * ghn);
    const float hprev = g_h[b * Hn + j];
    const float hn = (1.f - z) * n + z * hprev;

    hs[j] = hn;
    g_h[b * Hn + j] = hn;
    g_xcat[b * KX + 1024 + j] = hn;
    g_h_all[((size_t)t * Bn + b) * Hn + j] = hn;
    __syncthreads();

    // dec_proj for the NEXT step's attention
    const int wid = j >> 5, lane = j & 31;   // 16 warps
    for (int a = wid; a < An; a += 16) {
        const float* wr = W_dec + (size_t)a * Hn;
        float s = 0.f;
        for (int e = lane; e < Hn; e += 32) s += hs[e] * wr[e];
#pragma unroll
        for (int o = 16; o > 0; o >>= 1) s += __shfl_xor_sync(0xffffffffu, s, o);
        if (lane == 0) g_decproj[b * An + a] = s + b_dec[a];
    }
}

// ---------------------------------------------------------------------------
extern "C" void kernel_launch(void* const* d_in, const int* in_sizes, int n_in,
                              void* d_out, int out_size)
{
    (void)in_sizes; (void)n_in; (void)out_size;
    const float* enc     = (const float*)d_in[0];
    const float* pooled  = (const float*)d_in[1];
    const int*   traw    = (const int*)d_in[2];     // int32 or int64 (probed)
    const float* emb     = (const float*)d_in[3];
    const float* W_enc   = (const float*)d_in[4];
    const float* b_enc   = (const float*)d_in[5];
    const float* W_dec   = (const float*)d_in[6];
    const float* b_dec   = (const float*)d_in[7];
    const float* W_score = (const float*)d_in[8];
    /* d_in[9] b_score: softmax-invariant, unused */
    const float* W_ih    = (const float*)d_in[10];
    const float* W_hh    = (const float*)d_in[11];
    const float* b_ih    = (const float*)d_in[12];
    const float* b_hh    = (const float*)d_in[13];
    const float* W_out   = (const float*)d_in[14];
    const float* b_out   = (const float*)d_in[15];
    const float* W_init  = (const float*)d_in[16];
    const float* b_init  = (const float*)d_in[17];
    float* out = (float*)d_out;

    float *p_encproj, *p_hall, *p_xcat, *p_gpart, *p_wcat;
    cudaGetSymbolAddress((void**)&p_encproj, g_enc_proj);
    cudaGetSymbolAddress((void**)&p_hall,    g_h_all);
    cudaGetSymbolAddress((void**)&p_xcat,    g_xcat);
    cudaGetSymbolAddress((void**)&p_gpart,   g_gpart);
    cudaGetSymbolAddress((void**)&p_wcat,    g_Wcat);

    // Dtype probe (reads at most word index 2047 — safe for int32 or int64)
    detect_tok_dtype<<<1, 256>>>(traw);

    // Weight packing (idempotent each call)
    pack_wcat<<<(NG * KX + 255) / 256, 256>>>(W_ih, W_hh);
    pack_bcat<<<(NG + 255) / 256, 256>>>(b_ih, b_hh);

    // enc_proj = encoder_out @ W_enc.T + b_enc   (M=12544, N=256, K=512)
    gemm_tf32<128, 128, 0><<<dim3(An / 128, (Bn * Sn) / 128, 1), 256>>>(
        enc, W_enc, p_encproj, b_enc, Bn * Sn, An, En);

    setup_h0<<<Bn, 256>>>(pooled, W_init, b_init, W_dec, b_dec);

    for (int t = 0; t < Tn; t++) {
        attn_step<<<Bn, 256>>>(enc, W_score, traw, emb, t);
        // gates pre-activations: xcat(64x1536) @ Wcat(2048x1536).T, split-K
        gemm_tf32<64, 128, 1><<<dim3(NG / 128, 1, SPLITK), 256>>>(
            p_xcat, p_wcat, p_gpart, nullptr, Bn, NG, KX);
        gru_gates<<<Bn, Hn>>>(W_dec, b_dec, t);
    }

    // logits = h_all @ W_out.T + b_out   (M=1984, N=32000, K=512)
    gemm_tf32<128, 128, 2><<<dim3((Tn * Bn + 127) / 128, Vn / 128, 1), 256>>>(
        p_hall, W_out, out, b_out, Tn * Bn, Vn, Hn);
}

// round 7
// speedup vs baseline: 1.2271x; 1.2271x over previous
#include <cuda_runtime.h>
#include <cuda_fp16.h>
#include <cstdint>

#define DEV_INLINE __device__ __forceinline__

// Problem constants
constexpr int Bn = 64, Sn = 196, En = 512, Hn = 512, An = 256, Dn = 512,
              Vn = 32000, Ln = 32, Tn = 31;
constexpr int KX = 1536;   // xcat row: [embedded(512) | context(512) | h(512)]
constexpr int NG = 2048;   // GRU gemm N: [r(512) z(512) gi_n(512) gh_n(512)]
constexpr int SPLITK = 4;
constexpr int SCH = 16;                      // score rows per chunk
constexpr int NCH = (Sn + SCH - 1) / SCH;    // 13 chunks

// Scratch (device globals — no allocations allowed). 16B-aligned.
__device__ __align__(16) float g_enc_proj[Bn * Sn * An];
__device__ __align__(16) float g_h_all[2048 * Hn];
__device__ __align__(16) float g_xcat[Bn * KX];
__device__ __align__(16) float g_gpart[SPLITK * Bn * NG];
__device__ __align__(16) float g_h[Bn * Hn];
__device__ __align__(16) float g_decproj[Bn * An];
__device__ __align__(16) float g_Wcat[NG * KX];
__device__ __align__(16) float g_bcat[NG];
__device__ __align__(16) float g_scores[Bn * Sn];
__device__ int g_cnt[Bn];            // zero-init; reset after each use
__device__ int g_tok_is_i64;

DEV_INLINE float tanh_fast(float x) {
    float y; asm("tanh.approx.f32 %0, %1;" : "=f"(y) : "f"(x)); return y;
}
// Round-to-nearest tf32 conversion — REQUIRED: raw fp32 into mma.sync gets
// RZ-truncated by HW, whose coherent bias inflated rel_err to 1.17e-3.
DEV_INLINE unsigned f2tf32(float f) {
    unsigned u; asm("cvt.rna.tf32.f32 %0, %1;" : "=r"(u) : "f"(f)); return u;
}
DEV_INLINE void mma8(float c[4], const unsigned a[4], const unsigned b[2]) {
    asm volatile(
        "mma.sync.aligned.m16n8k8.row.col.f32.tf32.tf32.f32 "
        "{%0,%1,%2,%3}, {%4,%5,%6,%7}, {%8,%9}, {%0,%1,%2,%3};"
        : "+f"(c[0]), "+f"(c[1]), "+f"(c[2]), "+f"(c[3])
        : "r"(a[0]), "r"(a[1]), "r"(a[2]), "r"(a[3]), "r"(b[0]), "r"(b[1]));
}
DEV_INLINE void cp_async16(void* smem_dst, const void* gsrc) {
    unsigned dst = (unsigned)__cvta_generic_to_shared(smem_dst);
    asm volatile("cp.async.ca.shared.global [%0], [%1], 16;" :: "r"(dst), "l"(gsrc));
}

// ---------------------------------------------------------------------------
// targets dtype probe (bounded: max word index 2047 — safe for int32 or int64)
// ---------------------------------------------------------------------------
__global__ void detect_tok_dtype(const int* __restrict__ traw)
{
    __shared__ int any;
    if (threadIdx.x == 0) any = 0;
    __syncthreads();
    for (int i = threadIdx.x; i < (Bn * Ln) / 2; i += blockDim.x)
        if (traw[2 * i + 1] != 0) any = 1;
    __syncthreads();
    if (threadIdx.x == 0) g_tok_is_i64 = (any == 0) ? 1 : 0;
}

// ---------------------------------------------------------------------------
// tf32 GEMM, cp.async double-buffered, RNA-converted operands.
// MODE 0: C = acc + bias (row-major), guard m<M
// MODE 1: split-K partial store (+blockIdx.z*M*N)
// MODE 2: logits: row m -> (t=m/64, b=m%64): out[(b*31+t)*N + n] + bias
// ---------------------------------------------------------------------------
template <int BM, int BN, int MODE>
__global__ __launch_bounds__(256) void gemm_tf32(
    const float* __restrict__ A, const float* __restrict__ B,
    float* __restrict__ C, const float* __restrict__ bias,
    int M, int N, int K)
{
    constexpr int BK = 16;
    constexpr int LDS_ = BK + 4;           // 20 floats: 16B-aligned rows, conflict-free
    __shared__ float As[2][BM][LDS_];
    __shared__ float Bs[2][BN][LDS_];

    const int tid = threadIdx.x;
    const int lane = tid & 31;
    const int wid = tid >> 5;
    const int grp = lane >> 2;
    const int tig = lane & 3;

    constexpr int NWN = 4;                 // warps: 2 (m) x 4 (n)
    const int wm = wid / NWN;
    const int wn = wid % NWN;
    constexpr int WTM = BM / 2;
    constexpr int WTN = BN / 4;
    constexpr int MI = WTM / 16;
    constexpr int NI = WTN / 8;

    int mblk, nblk;
    if (MODE == 2) { mblk = blockIdx.x; nblk = blockIdx.y; }
    else           { mblk = blockIdx.y; nblk = blockIdx.x; }

    const int kchunk = K / gridDim.z;
    const int kbase  = blockIdx.z * kchunk;
    const int kIters = kchunk / BK;

    const int lr = tid >> 2;               // 0..63
    const int lc = (tid & 3) * 4;          // 0,4,8,12
    constexpr int LA = BM / 64;
    constexpr int LB = BN / 64;

    auto issueTile = [&](int kt, int st) {
        const int kg = kbase + kt * BK + lc;
#pragma unroll
        for (int i = 0; i < LA; i++) {
            int gr = mblk * BM + lr + i * 64;
            if (gr >= M) gr = M - 1;
            cp_async16(&As[st][lr + i * 64][lc], A + (size_t)gr * K + kg);
        }
#pragma unroll
        for (int i = 0; i < LB; i++) {
            int gr = nblk * BN + lr + i * 64;
            cp_async16(&Bs[st][lr + i * 64][lc], B + (size_t)gr * K + kg);
        }
        asm volatile("cp.async.commit_group;");
    };

    float acc[MI][NI][4];
#pragma unroll
    for (int mi = 0; mi < MI; mi++)
#pragma unroll
        for (int ni = 0; ni < NI; ni++)
#pragma unroll
            for (int q = 0; q < 4; q++) acc[mi][ni][q] = 0.f;

    issueTile(0, 0);
    for (int kt = 0; kt < kIters; kt++) {
        asm volatile("cp.async.wait_group 0;" ::: "memory");
        __syncthreads();
        if (kt + 1 < kIters) issueTile(kt + 1, (kt + 1) & 1);
        const int st = kt & 1;

#pragma unroll
        for (int ks = 0; ks < 2; ks++) {
            const int k0 = ks * 8;
            unsigned af[MI][4];
#pragma unroll
            for (int mi = 0; mi < MI; mi++) {
                const int r = wm * WTM + mi * 16 + grp;
                af[mi][0] = f2tf32(As[st][r][k0 + tig]);
                af[mi][1] = f2tf32(As[st][r + 8][k0 + tig]);
                af[mi][2] = f2tf32(As[st][r][k0 + tig + 4]);
                af[mi][3] = f2tf32(As[st][r + 8][k0 + tig + 4]);
            }
            unsigned bf[NI][2];
#pragma unroll
            for (int ni = 0; ni < NI; ni++) {
                const int c = wn * WTN + ni * 8 + grp;
                bf[ni][0] = f2tf32(Bs[st][c][k0 + tig]);
                bf[ni][1] = f2tf32(Bs[st][c][k0 + tig + 4]);
            }
#pragma unroll
            for (int mi = 0; mi < MI; mi++)
#pragma unroll
                for (int ni = 0; ni < NI; ni++)
                    mma8(acc[mi][ni], af[mi], bf[ni]);
        }
        __syncthreads();   // protect stage st before it is refilled at kt+2
    }

    float* Cp = C;
    if (MODE == 1) Cp = C + (size_t)blockIdx.z * M * N;
#pragma unroll
    for (int mi = 0; mi < MI; mi++) {
#pragma unroll
        for (int ni = 0; ni < NI; ni++) {
            const int r0 = mblk * BM + wm * WTM + mi * 16 + grp;
            const int c0 = nblk * BN + wn * WTN + ni * 8 + tig * 2;
#pragma unroll
            for (int hh = 0; hh < 2; hh++) {
                const int r = r0 + hh * 8;
                const float v0 = acc[mi][ni][hh * 2 + 0];
                const float v1 = acc[mi][ni][hh * 2 + 1];
                if (MODE == 0) {
                    if (r < M) {
                        Cp[(size_t)r * N + c0]     = v0 + bias[c0];
                        Cp[(size_t)r * N + c0 + 1] = v1 + bias[c0 + 1];
                    }
                } else if (MODE == 1) {
                    Cp[(size_t)r * N + c0]     = v0;
                    Cp[(size_t)r * N + c0 + 1] = v1;
                } else {
                    if (r < M) {
                        const int tt = r >> 6, bb = r & 63;
                        const size_t o = ((size_t)bb * Tn + tt) * (size_t)N + c0;
                        Cp[o]     = v0 + bias[c0];
                        Cp[o + 1] = v1 + bias[c0 + 1];
                    }
                }
            }
        }
    }
}

// ---------------------------------------------------------------------------
// Weight packing (idempotent each launch)
// ---------------------------------------------------------------------------
__global__ void pack_wcat(const float* __restrict__ W_ih,
                          const float* __restrict__ W_hh)
{
    const int idx = blockIdx.x * blockDim.x + threadIdx.x;
    if (idx >= NG * KX) return;
    const int j = idx / KX, k = idx - j * KX;
    float v = 0.f;
    if (j < 1536) {
        if (k < 1024) v = W_ih[(size_t)j * 1024 + k];
        else if (j < 1024) v = W_hh[(size_t)j * 512 + (k - 1024)];
    } else {
        if (k >= 1024) v = W_hh[(size_t)(j - 512) * 512 + (k - 1024)];
    }
    g_Wcat[idx] = v;
}

__global__ void pack_bcat(const float* __restrict__ b_ih,
                          const float* __restrict__ b_hh)
{
    const int j = blockIdx.x * blockDim.x + threadIdx.x;
    if (j >= NG) return;
    float v;
    if (j < 1024)      v = b_ih[j] + b_hh[j];
    else if (j < 1536) v = b_ih[j];
    else               v = b_hh[j - 512];
    g_bcat[j] = v;
}

// ---------------------------------------------------------------------------
// Setup: h0 = tanh(pooled @ W_init.T + b_init); dec_proj(h0) + b_dec
// ---------------------------------------------------------------------------
__global__ void setup_h0(const float* __restrict__ pooled,
                         const float* __restrict__ W_init,
                         const float* __restrict__ b_init,
                         const float* __restrict__ W_dec,
                         const float* __restrict__ b_dec)
{
    __shared__ float h0s[Hn];
    const int b = blockIdx.x;
    const int tid = threadIdx.x, wid = tid >> 5, lane = tid & 31;
    const float* pb = pooled + (size_t)b * En;

    for (int j = wid; j < Hn; j += 8) {
        const float* wr = W_init + (size_t)j * En;
        float s = 0.f;
        for (int e = lane; e < En; e += 32) s += pb[e] * wr[e];
#pragma unroll
        for (int o = 16; o > 0; o >>= 1) s += __shfl_xor_sync(0xffffffffu, s, o);
        if (lane == 0) h0s[j] = tanhf(s + b_init[j]);
    }
    __syncthreads();
    for (int j = tid; j < Hn; j += blockDim.x) {
        const float v = h0s[j];
        g_h[b * Hn + j] = v;
        g_xcat[b * KX + 1024 + j] = v;
    }
    for (int a = wid; a < An; a += 8) {
        const float* wr = W_dec + (size_t)a * Hn;
        float s = 0.f;
        for (int e = lane; e < Hn; e += 32) s += h0s[e] * wr[e];
#pragma unroll
        for (int o = 16; o > 0; o >>= 1) s += __shfl_xor_sync(0xffffffffu, s, o);
        if (lane == 0) g_decproj[b * An + a] = s + b_dec[a];
    }
}

// ---------------------------------------------------------------------------
// Attention, chip-wide: grid (Bn, NCH). fp32 scores (tanh.approx.f32); last
// CTA per batch (atomic counter) does softmax + context + embedding gather.
// ---------------------------------------------------------------------------
__global__ __launch_bounds__(256) void attn_fused(
    const float* __restrict__ enc, const float* __restrict__ W_score,
    const int* __restrict__ traw, const float* __restrict__ emb, int t)
{
    __shared__ float dp[An];
    __shared__ float w[Sn];
    __shared__ float red[8];
    __shared__ int lastFlag;
    const int b = blockIdx.x, ch = blockIdx.y;
    const int tid = threadIdx.x, wid = tid >> 5, lane = tid & 31;

    dp[tid] = g_decproj[b * An + tid];   // blockDim == An == 256
    __syncthreads();

    // phase 1: partial scores for this chunk (fp32 energies, approx tanh)
    const int sHi = min(ch * SCH + SCH, Sn);
    for (int s = ch * SCH + wid; s < sHi; s += 8) {
        const float* er = g_enc_proj + ((size_t)b * Sn + s) * An;
        float sc = 0.f;
#pragma unroll
        for (int a = lane; a < An; a += 32)
            sc += tanh_fast(er[a] + dp[a]) * W_score[a];
#pragma unroll
        for (int o = 16; o > 0; o >>= 1) sc += __shfl_xor_sync(0xffffffffu, sc, o);
        if (lane == 0) g_scores[b * Sn + s] = sc;
    }

    // arrive (release) + elect last CTA for this b
    __threadfence();
    __syncthreads();
    if (tid == 0) {
        const int old = atomicAdd(&g_cnt[b], 1);
        lastFlag = (old == NCH - 1);
        if (lastFlag) g_cnt[b] = 0;     // reset for next step / next replay
    }
    __syncthreads();
    if (!lastFlag) return;
    __threadfence();                     // acquire

    // phase 2 (one CTA per b): embedding gather
    {
        const int i = b * Ln + t;
        int tok = g_tok_is_i64 ? traw[2 * i] : traw[i];
        if (tok < 0) tok = 0;
        if (tok >= Vn) tok = Vn - 1;
        const float* er = emb + (size_t)tok * Dn;
        const bool pad = (tok == 2);
        for (int d = tid; d < Dn; d += blockDim.x)
            g_xcat[b * KX + d] = pad ? 0.f : er[d];
    }

    // softmax over S
    const float v = (tid < Sn) ? g_scores[b * Sn + tid] : -1e30f;
    float mx = v;
#pragma unroll
    for (int o = 16; o > 0; o >>= 1) mx = fmaxf(mx, __shfl_xor_sync(0xffffffffu, mx, o));
    if (lane == 0) red[wid] = mx;
    __syncthreads();
    float gmx = red[0];
#pragma unroll
    for (int i = 1; i < 8; i++) gmx = fmaxf(gmx, red[i]);
    __syncthreads();
    const float ev = (tid < Sn) ? __expf(v - gmx) : 0.f;
    float sm = ev;
#pragma unroll
    for (int o = 16; o > 0; o >>= 1) sm += __shfl_xor_sync(0xffffffffu, sm, o);
    if (lane == 0) red[wid] = sm;
    __syncthreads();
    float tot = 0.f;
#pragma unroll
    for (int i = 0; i < 8; i++) tot += red[i];
    if (tid < Sn) w[tid] = ev * (1.f / tot);
    __syncthreads();

    // context[e] = sum_s w[s] * enc[b,s,e]
    const float* eb = enc + (size_t)b * Sn * En;
    for (int e0 = tid; e0 < En; e0 += blockDim.x) {
        float acc = 0.f;
#pragma unroll 4
        for (int s = 0; s < Sn; s++) acc += w[s] * eb[(size_t)s * En + e0];
        g_xcat[b * KX + 512 + e0] = acc;
    }
}

// ---------------------------------------------------------------------------
// Gates: combine split-K partials + biases -> h_new; also dec_proj(h_new)
// ---------------------------------------------------------------------------
__global__ void gru_gates(const float* __restrict__ W_dec,
                          const float* __restrict__ b_dec, int t)
{
    __shared__ float hs[Hn];
    const int b = blockIdx.x;
    const int j = threadIdx.x;   // 512 threads == Hn

    float rp  = g_bcat[j];
    float zp  = g_bcat[512 + j];
    float gin = g_bcat[1024 + j];
    float ghn = g_bcat[1536 + j];
#pragma unroll
    for (int p = 0; p < SPLITK; p++) {
        const float* gp = g_gpart + (size_t)p * Bn * NG + (size_t)b * NG;
        rp  += gp[j];
        zp  += gp[512 + j];
        gin += gp[1024 + j];
        ghn += gp[1536 + j];
    }
    const float r = 1.f / (1.f + expf(-rp));
    const float z = 1.f / (1.f + expf(-zp));
    const float n = tanhf(gin + r * ghn);
    const float hprev = g_h[b * Hn + j];
    const float hn = (1.f - z) * n + z * hprev;

    hs[j] = hn;
    g_h[b * Hn + j] = hn;
    g_xcat[b * KX + 1024 + j] = hn;
    g_h_all[((size_t)t * Bn + b) * Hn + j] = hn;
    __syncthreads();

    const int wid = j >> 5, lane = j & 31;   // 16 warps
    for (int a = wid; a < An; a += 16) {
        const float* wr = W_dec + (size_t)a * Hn;
        float s = 0.f;
        for (int e = lane; e < Hn; e += 32) s += hs[e] * wr[e];
#pragma unroll
        for (int o = 16; o > 0; o >>= 1) s += __shfl_xor_sync(0xffffffffu, s, o);
        if (lane == 0) g_decproj[b * An + a] = s + b_dec[a];
    }
}

// ---------------------------------------------------------------------------
extern "C" void kernel_launch(void* const* d_in, const int* in_sizes, int n_in,
                              void* d_out, int out_size)
{
    (void)in_sizes; (void)n_in; (void)out_size;
    const float* enc     = (const float*)d_in[0];
    const float* pooled  = (const float*)d_in[1];
    const int*   traw    = (const int*)d_in[2];
    const float* emb     = (const float*)d_in[3];
    const float* W_enc   = (const float*)d_in[4];
    const float* b_enc   = (const float*)d_in[5];
    const float* W_dec   = (const float*)d_in[6];
    const float* b_dec   = (const float*)d_in[7];
    const float* W_score = (const float*)d_in[8];
    const float* W_ih    = (const float*)d_in[10];
    const float* W_hh    = (const float*)d_in[11];
    const float* b_ih    = (const float*)d_in[12];
    const float* b_hh    = (const float*)d_in[13];
    const float* W_out   = (const float*)d_in[14];
    const float* b_out   = (const float*)d_in[15];
    const float* W_init  = (const float*)d_in[16];
    const float* b_init  = (const float*)d_in[17];
    float* out = (float*)d_out;

    float *p_encproj, *p_hall, *p_xcat, *p_gpart, *p_wcat;
    cudaGetSymbolAddress((void**)&p_encproj, g_enc_proj);
    cudaGetSymbolAddress((void**)&p_hall,    g_h_all);
    cudaGetSymbolAddress((void**)&p_xcat,    g_xcat);
    cudaGetSymbolAddress((void**)&p_gpart,   g_gpart);
    cudaGetSymbolAddress((void**)&p_wcat,    g_Wcat);

    detect_tok_dtype<<<1, 256>>>(traw);
    pack_wcat<<<(NG * KX + 255) / 256, 256>>>(W_ih, W_hh);
    pack_bcat<<<(NG + 255) / 256, 256>>>(b_ih, b_hh);

    // enc_proj: M=12544, N=256, K=512 (fp32 out)
    gemm_tf32<128, 128, 0><<<dim3(An / 128, (Bn * Sn) / 128, 1), 256>>>(
        enc, W_enc, p_encproj, b_enc, Bn * Sn, An, En);

    setup_h0<<<Bn, 256>>>(pooled, W_init, b_init, W_dec, b_dec);

    for (int t = 0; t < Tn; t++) {
        attn_fused<<<dim3(Bn, NCH), 256>>>(enc, W_score, traw, emb, t);
        gemm_tf32<64, 128, 1><<<dim3(NG / 128, 1, SPLITK), 256>>>(
            p_xcat, p_wcat, p_gpart, nullptr, Bn, NG, KX);
        gru_gates<<<Bn, Hn>>>(W_dec, b_dec, t);
    }

    // logits: M=1984, N=32000, K=512
    gemm_tf32<128, 128, 2><<<dim3((Tn * Bn + 127) / 128, Vn / 128, 1), 256>>>(
        p_hall, W_out, out, b_out, Tn * Bn, Vn, Hn);
}

// round 9
// speedup vs baseline: 1.5177x; 1.2369x over previous
#include <cuda_runtime.h>
#include <cstdint>

#define DEV_INLINE __device__ __forceinline__

// Problem constants
constexpr int Bn = 64, Sn = 196, En = 512, Hn = 512, An = 256, Dn = 512,
              Vn = 32000, Ln = 32, Tn = 31;
constexpr int KX = 1536;   // xcat row: [embedded(512) | context(512) | h(512)]
constexpr int NG = 2048;   // GRU gemm N: [r(512) z(512) gi_n(512) gh_n(512)]
constexpr int NSPL = 8;    // split-K factor inside persistent kernel
constexpr int SCH = 16;                      // score rows per chunk
constexpr int NCH = (Sn + SCH - 1) / SCH;    // 13 chunks
constexpr int GP = 128;    // persistent grid (single wave guaranteed: <148 SMs)

// Scratch (device globals). 16B-aligned.
__device__ __align__(16) float g_enc_proj[Bn * Sn * An];
__device__ __align__(16) float g_h_all[2048 * Hn];
__device__ __align__(16) float g_xcat[Bn * KX];
__device__ __align__(16) float g_gpart[NSPL * Bn * NG];
__device__ __align__(16) float g_hbuf[2][Bn * Hn];      // double-buffered h
__device__ __align__(16) float g_decproj[Bn * An];
__device__ __align__(16) float g_Wcat[NG * KX];
__device__ __align__(16) float g_bcat[NG];
__device__ __align__(16) float g_scores[Bn * Sn];
__device__ int g_tok_is_i64;
__device__ int g_bar_cnt;
__device__ int g_bar_sense;

DEV_INLINE float tanh_fast(float x) {
    float y; asm("tanh.approx.f32 %0, %1;" : "=f"(y) : "f"(x)); return y;
}
// Round-to-nearest tf32 conversion — REQUIRED (HW RZ truncation bias -> 1.17e-3)
DEV_INLINE unsigned f2tf32(float f) {
    unsigned u; asm("cvt.rna.tf32.f32 %0, %1;" : "=r"(u) : "f"(f)); return u;
}
DEV_INLINE void mma8(float c[4], const unsigned a[4], const unsigned b[2]) {
    asm volatile(
        "mma.sync.aligned.m16n8k8.row.col.f32.tf32.tf32.f32 "
        "{%0,%1,%2,%3}, {%4,%5,%6,%7}, {%8,%9}, {%0,%1,%2,%3};"
        : "+f"(c[0]), "+f"(c[1]), "+f"(c[2]), "+f"(c[3])
        : "r"(a[0]), "r"(a[1]), "r"(a[2]), "r"(a[3]), "r"(b[0]), "r"(b[1]));
}
DEV_INLINE void cp_async16(void* smem_dst, const void* gsrc) {
    unsigned dst = (unsigned)__cvta_generic_to_shared(smem_dst);
    asm volatile("cp.async.ca.shared.global [%0], [%1], 16;" :: "r"(dst), "l"(gsrc));
}

// ---------------------------------------------------------------------------
__global__ void reset_bar() { g_bar_cnt = 0; g_bar_sense = 0; }

__global__ void detect_tok_dtype(const int* __restrict__ traw)
{
    __shared__ int any;
    if (threadIdx.x == 0) any = 0;
    __syncthreads();
    for (int i = threadIdx.x; i < (Bn * Ln) / 2; i += blockDim.x)
        if (traw[2 * i + 1] != 0) any = 1;
    __syncthreads();
    if (threadIdx.x == 0) g_tok_is_i64 = (any == 0) ? 1 : 0;
}

// ---------------------------------------------------------------------------
// Standalone tf32 GEMM (enc_proj MODE 0, logits MODE 2), unchanged from R7.
// ---------------------------------------------------------------------------
template <int BM, int BN, int MODE>
__global__ __launch_bounds__(256) void gemm_tf32(
    const float* __restrict__ A, const float* __restrict__ B,
    float* __restrict__ C, const float* __restrict__ bias,
    int M, int N, int K)
{
    constexpr int BK = 16;
    constexpr int LDS_ = BK + 4;
    __shared__ float As[2][BM][LDS_];
    __shared__ float Bs[2][BN][LDS_];

    const int tid = threadIdx.x;
    const int lane = tid & 31;
    const int wid = tid >> 5;
    const int grp = lane >> 2;
    const int tig = lane & 3;

    constexpr int NWN = 4;
    const int wm = wid / NWN;
    const int wn = wid % NWN;
    constexpr int WTM = BM / 2;
    constexpr int WTN = BN / 4;
    constexpr int MI = WTM / 16;
    constexpr int NI = WTN / 8;

    int mblk, nblk;
    if (MODE == 2) { mblk = blockIdx.x; nblk = blockIdx.y; }
    else           { mblk = blockIdx.y; nblk = blockIdx.x; }

    const int kIters = K / BK;
    const int lr = tid >> 2;
    const int lc = (tid & 3) * 4;
    constexpr int LA = BM / 64;
    constexpr int LB = BN / 64;

    auto issueTile = [&](int kt, int st) {
        const int kg = kt * BK + lc;
#pragma unroll
        for (int i = 0; i < LA; i++) {
            int gr = mblk * BM + lr + i * 64;
            if (gr >= M) gr = M - 1;
            cp_async16(&As[st][lr + i * 64][lc], A + (size_t)gr * K + kg);
        }
#pragma unroll
        for (int i = 0; i < LB; i++) {
            int gr = nblk * BN + lr + i * 64;
            cp_async16(&Bs[st][lr + i * 64][lc], B + (size_t)gr * K + kg);
        }
        asm volatile("cp.async.commit_group;");
    };

    float acc[MI][NI][4];
#pragma unroll
    for (int mi = 0; mi < MI; mi++)
#pragma unroll
        for (int ni = 0; ni < NI; ni++)
#pragma unroll
            for (int q = 0; q < 4; q++) acc[mi][ni][q] = 0.f;

    issueTile(0, 0);
    for (int kt = 0; kt < kIters; kt++) {
        asm volatile("cp.async.wait_group 0;" ::: "memory");
        __syncthreads();
        if (kt + 1 < kIters) issueTile(kt + 1, (kt + 1) & 1);
        const int st = kt & 1;

#pragma unroll
        for (int ks = 0; ks < 2; ks++) {
            const int k0 = ks * 8;
            unsigned af[MI][4];
#pragma unroll
            for (int mi = 0; mi < MI; mi++) {
                const int r = wm * WTM + mi * 16 + grp;
                af[mi][0] = f2tf32(As[st][r][k0 + tig]);
                af[mi][1] = f2tf32(As[st][r + 8][k0 + tig]);
                af[mi][2] = f2tf32(As[st][r][k0 + tig + 4]);
                af[mi][3] = f2tf32(As[st][r + 8][k0 + tig + 4]);
            }
            unsigned bf[NI][2];
#pragma unroll
            for (int ni = 0; ni < NI; ni++) {
                const int c = wn * WTN + ni * 8 + grp;
                bf[ni][0] = f2tf32(Bs[st][c][k0 + tig]);
                bf[ni][1] = f2tf32(Bs[st][c][k0 + tig + 4]);
            }
#pragma unroll
            for (int mi = 0; mi < MI; mi++)
#pragma unroll
                for (int ni = 0; ni < NI; ni++)
                    mma8(acc[mi][ni], af[mi], bf[ni]);
        }
        __syncthreads();
    }

#pragma unroll
    for (int mi = 0; mi < MI; mi++) {
#pragma unroll
        for (int ni = 0; ni < NI; ni++) {
            const int r0 = mblk * BM + wm * WTM + mi * 16 + grp;
            const int c0 = nblk * BN + wn * WTN + ni * 8 + tig * 2;
#pragma unroll
            for (int hh = 0; hh < 2; hh++) {
                const int r = r0 + hh * 8;
                const float v0 = acc[mi][ni][hh * 2 + 0];
                const float v1 = acc[mi][ni][hh * 2 + 1];
                if (MODE == 0) {
                    if (r < M) {
                        C[(size_t)r * N + c0]     = v0 + bias[c0];
                        C[(size_t)r * N + c0 + 1] = v1 + bias[c0 + 1];
                    }
                } else {
                    if (r < M) {
                        const int tt = r >> 6, bb = r & 63;
                        const size_t o = ((size_t)bb * Tn + tt) * (size_t)N + c0;
                        C[o]     = v0 + bias[c0];
                        C[o + 1] = v1 + bias[c0 + 1];
                    }
                }
            }
        }
    }
}

// ---------------------------------------------------------------------------
// Weight packing (idempotent each launch)
// ---------------------------------------------------------------------------
__global__ void pack_wcat(const float* __restrict__ W_ih,
                          const float* __restrict__ W_hh)
{
    const int idx = blockIdx.x * blockDim.x + threadIdx.x;
    if (idx >= NG * KX) return;
    const int j = idx / KX, k = idx - j * KX;
    float v = 0.f;
    if (j < 1536) {
        if (k < 1024) v = W_ih[(size_t)j * 1024 + k];
        else if (j < 1024) v = W_hh[(size_t)j * 512 + (k - 1024)];
    } else {
        if (k >= 1024) v = W_hh[(size_t)(j - 512) * 512 + (k - 1024)];
    }
    g_Wcat[idx] = v;
}

__global__ void pack_bcat(const float* __restrict__ b_ih,
                          const float* __restrict__ b_hh)
{
    const int j = blockIdx.x * blockDim.x + threadIdx.x;
    if (j >= NG) return;
    float v;
    if (j < 1024)      v = b_ih[j] + b_hh[j];
    else if (j < 1536) v = b_ih[j];
    else               v = b_hh[j - 512];
    g_bcat[j] = v;
}

// ---------------------------------------------------------------------------
// Setup: h0 = tanh(pooled @ W_init.T + b_init); dec_proj(h0) + b_dec
// ---------------------------------------------------------------------------
__global__ void setup_h0(const float* __restrict__ pooled,
                         const float* __restrict__ W_init,
                         const float* __restrict__ b_init,
                         const float* __restrict__ W_dec,
                         const float* __restrict__ b_dec)
{
    __shared__ float h0s[Hn];
    const int b = blockIdx.x;
    const int tid = threadIdx.x, wid = tid >> 5, lane = tid & 31;
    const float* pb = pooled + (size_t)b * En;

    for (int j = wid; j < Hn; j += 8) {
        const float* wr = W_init + (size_t)j * En;
        float s = 0.f;
        for (int e = lane; e < En; e += 32) s += pb[e] * wr[e];
#pragma unroll
        for (int o = 16; o > 0; o >>= 1) s += __shfl_xor_sync(0xffffffffu, s, o);
        if (lane == 0) h0s[j] = tanhf(s + b_init[j]);
    }
    __syncthreads();
    for (int j = tid; j < Hn; j += blockDim.x) {
        const float v = h0s[j];
        g_hbuf[0][b * Hn + j] = v;
        g_xcat[b * KX + 1024 + j] = v;
    }
    for (int a = wid; a < An; a += 8) {
        const float* wr = W_dec + (size_t)a * Hn;
        float s = 0.f;
        for (int e = lane; e < Hn; e += 32) s += h0s[e] * wr[e];
#pragma unroll
        for (int o = 16; o > 0; o >>= 1) s += __shfl_xor_sync(0xffffffffu, s, o);
        if (lane == 0) g_decproj[b * An + a] = s + b_dec[a];
    }
}

// ---------------------------------------------------------------------------
// Persistent recurrent kernel: all Tn steps, 4 grid barriers per step.
// GP=128 CTAs x 256 threads — single wave guaranteed (128 < 148 SMs).
// ---------------------------------------------------------------------------
__global__ __launch_bounds__(256) void recurrent_persistent(
    const float* __restrict__ enc, const float* __restrict__ W_score,
    const int* __restrict__ traw, const float* __restrict__ emb,
    const float* __restrict__ W_dec, const float* __restrict__ b_dec)
{
    // smem (all phases; ~35 KB total)
    __shared__ float As3[2][64][20];
    __shared__ float Bs3[2][128][20];
    __shared__ float dp[An];
    __shared__ float w[256];
    __shared__ float hs[Hn];
    __shared__ float red[8];
    __shared__ int sSense;

    const int tid = threadIdx.x;
    const int lane = tid & 31;
    const int wid = tid >> 5;
    const int grp = lane >> 2;
    const int tig = lane & 3;

    if (tid == 0) sSense = 0;
    __syncthreads();

    auto gbar = [&]() {
        __syncthreads();
        if (tid == 0) {
            __threadfence();
            const int target = sSense ^ 1;
            if (atomicAdd(&g_bar_cnt, 1) == GP - 1) {
                g_bar_cnt = 0;
                __threadfence();
                atomicExch(&g_bar_sense, target);
            } else {
                while (*(volatile int*)&g_bar_sense != target) { }
            }
            __threadfence();
            sSense = target;
        }
        __syncthreads();
    };

    for (int t = 0; t < Tn; t++) {
        const int par = t & 1;

        // ---- Phase 1: scores (Bn*NCH = 832 chunk units) ----
        for (int u = blockIdx.x; u < Bn * NCH; u += GP) {
            const int b = u / NCH, ch = u - b * NCH;
            dp[tid] = g_decproj[b * An + tid];
            __syncthreads();
            const int sLo = ch * SCH, sHi = min(sLo + SCH, Sn);
            for (int s = sLo + wid; s < sHi; s += 8) {
                const float* er = g_enc_proj + ((size_t)b * Sn + s) * An;
                float sc = 0.f;
#pragma unroll
                for (int a = lane; a < An; a += 32)
                    sc += tanh_fast(er[a] + dp[a]) * W_score[a];
#pragma unroll
                for (int o = 16; o > 0; o >>= 1)
                    sc += __shfl_xor_sync(0xffffffffu, sc, o);
                if (lane == 0) g_scores[b * Sn + s] = sc;
            }
            __syncthreads();
        }
        gbar();

        // ---- Phase 2: softmax + context + embed (2 CTAs per batch) ----
        {
            const int u = blockIdx.x;            // GP == 2*Bn exactly
            const int b = u >> 1, half = u & 1;

            if (half == 0) {   // embedding gather (padding_idx=2 -> zeros)
                const int i = b * Ln + t;
                int tok = g_tok_is_i64 ? traw[2 * i] : traw[i];
                if (tok < 0) tok = 0;
                if (tok >= Vn) tok = Vn - 1;
                const float* er = emb + (size_t)tok * Dn;
                const bool pad = (tok == 2);
                for (int d = tid; d < Dn; d += 256)
                    g_xcat[b * KX + d] = pad ? 0.f : er[d];
            }

            // softmax (redundant in both halves; deterministic identical)
            const float v = (tid < Sn) ? g_scores[b * Sn + tid] : -1e30f;
            float mx = v;
#pragma unroll
            for (int o = 16; o > 0; o >>= 1)
                mx = fmaxf(mx, __shfl_xor_sync(0xffffffffu, mx, o));
            if (lane == 0) red[wid] = mx;
            __syncthreads();
            float gmx = red[0];
#pragma unroll
            for (int i = 1; i < 8; i++) gmx = fmaxf(gmx, red[i]);
            __syncthreads();
            const float ev = (tid < Sn) ? __expf(v - gmx) : 0.f;
            float sm = ev;
#pragma unroll
            for (int o = 16; o > 0; o >>= 1)
                sm += __shfl_xor_sync(0xffffffffu, sm, o);
            if (lane == 0) red[wid] = sm;
            __syncthreads();
            float tot = 0.f;
#pragma unroll
            for (int i = 0; i < 8; i++) tot += red[i];
            if (tid < Sn) w[tid] = ev * (1.f / tot);
            __syncthreads();

            // context over this half's 256 e-columns
            const int e0 = half * 256 + tid;
            const float* eb = enc + (size_t)b * Sn * En;
            float acc = 0.f;
#pragma unroll 4
            for (int s = 0; s < Sn; s++) acc += w[s] * eb[(size_t)s * En + e0];
            g_xcat[b * KX + 512 + e0] = acc;
            __syncthreads();
        }
        gbar();

        // ---- Phase 3: GRU gates GEMM (16 ntiles x 8 splits = 128 units) ----
        {
            const int u = blockIdx.x;            // one unit per CTA
            const int nblk = u >> 3, split = u & 7;
            const int kbase = split * (KX / NSPL);        // 192
            constexpr int kIters = (KX / NSPL) / 16;      // 12
            const int wm = wid >> 2, wn = wid & 3;        // 2 x 4 warps
            const int lr = tid >> 2, lc = (tid & 3) * 4;

            auto issue3 = [&](int kt, int st) {
                const int kg = kbase + kt * 16 + lc;
                cp_async16(&As3[st][lr][lc], g_xcat + (size_t)lr * KX + kg);
                cp_async16(&Bs3[st][lr][lc],
                           g_Wcat + (size_t)(nblk * 128 + lr) * KX + kg);
                cp_async16(&Bs3[st][lr + 64][lc],
                           g_Wcat + (size_t)(nblk * 128 + lr + 64) * KX + kg);
                asm volatile("cp.async.commit_group;");
            };

            float acc[2][4][4];
#pragma unroll
            for (int mi = 0; mi < 2; mi++)
#pragma unroll
                for (int ni = 0; ni < 4; ni++)
#pragma unroll
                    for (int q = 0; q < 4; q++) acc[mi][ni][q] = 0.f;

            issue3(0, 0);
            for (int kt = 0; kt < kIters; kt++) {
                asm volatile("cp.async.wait_group 0;" ::: "memory");
                __syncthreads();
                if (kt + 1 < kIters) issue3(kt + 1, (kt + 1) & 1);
                const int st = kt & 1;
#pragma unroll
                for (int ks = 0; ks < 2; ks++) {
                    const int k0 = ks * 8;
                    unsigned af[2][4];
#pragma unroll
                    for (int mi = 0; mi < 2; mi++) {
                        const int r = wm * 32 + mi * 16 + grp;
                        af[mi][0] = f2tf32(As3[st][r][k0 + tig]);
                        af[mi][1] = f2tf32(As3[st][r + 8][k0 + tig]);
                        af[mi][2] = f2tf32(As3[st][r][k0 + tig + 4]);
                        af[mi][3] = f2tf32(As3[st][r + 8][k0 + tig + 4]);
                    }
                    unsigned bf[4][2];
#pragma unroll
                    for (int ni = 0; ni < 4; ni++) {
                        const int c = wn * 32 + ni * 8 + grp;
                        bf[ni][0] = f2tf32(Bs3[st][c][k0 + tig]);
                        bf[ni][1] = f2tf32(Bs3[st][c][k0 + tig + 4]);
                    }
#pragma unroll
                    for (int mi = 0; mi < 2; mi++)
#pragma unroll
                        for (int ni = 0; ni < 4; ni++)
                            mma8(acc[mi][ni], af[mi], bf[ni]);
                }
                __syncthreads();
            }

            float* gp = g_gpart + (size_t)split * Bn * NG;
#pragma unroll
            for (int mi = 0; mi < 2; mi++)
#pragma unroll
                for (int ni = 0; ni < 4; ni++) {
                    const int r0 = wm * 32 + mi * 16 + grp;
                    const int c0 = nblk * 128 + wn * 32 + ni * 8 + tig * 2;
#pragma unroll
                    for (int hh = 0; hh < 2; hh++) {
                        const int r = r0 + hh * 8;
                        gp[(size_t)r * NG + c0]     = acc[mi][ni][hh * 2 + 0];
                        gp[(size_t)r * NG + c0 + 1] = acc[mi][ni][hh * 2 + 1];
                    }
                }
        }
        gbar();

        // ---- Phase 4: gates (redundant per half) + decproj halves ----
        {
            const int u = blockIdx.x;
            const int b = u >> 1, ah = u & 1;
#pragma unroll
            for (int jj = 0; jj < 2; jj++) {
                const int j = tid + jj * 256;
                float rp  = g_bcat[j];
                float zp  = g_bcat[512 + j];
                float gin = g_bcat[1024 + j];
                float ghn = g_bcat[1536 + j];
#pragma unroll
                for (int p = 0; p < NSPL; p++) {
                    const float* gp = g_gpart + ((size_t)p * Bn + b) * NG;
                    rp  += gp[j];
                    zp  += gp[512 + j];
                    gin += gp[1024 + j];
                    ghn += gp[1536 + j];
                }
                const float r = 1.f / (1.f + expf(-rp));
                const float z = 1.f / (1.f + expf(-zp));
                const float n = tanhf(gin + r * ghn);
                const float hprev = g_hbuf[par][b * Hn + j];
                const float hn = (1.f - z) * n + z * hprev;
                hs[j] = hn;
                if (ah == 0) {
                    g_hbuf[par ^ 1][b * Hn + j] = hn;
                    g_xcat[b * KX + 1024 + j] = hn;
                    g_h_all[((size_t)t * Bn + b) * Hn + j] = hn;
                }
            }
            __syncthreads();

            // dec_proj for next step: this CTA's half of the a-range
            for (int a = ah * 128 + wid; a < ah * 128 + 128; a += 8) {
                const float* wr = W_dec + (size_t)a * Hn;
                float s = 0.f;
                for (int e = lane; e < Hn; e += 32) s += hs[e] * wr[e];
#pragma unroll
                for (int o = 16; o > 0; o >>= 1)
                    s += __shfl_xor_sync(0xffffffffu, s, o);
                if (lane == 0) g_decproj[b * An + a] = s + b_dec[a];
            }
            __syncthreads();
        }
        gbar();
    }
}

// ---------------------------------------------------------------------------
extern "C" void kernel_launch(void* const* d_in, const int* in_sizes, int n_in,
                              void* d_out, int out_size)
{
    (void)in_sizes; (void)n_in; (void)out_size;
    const float* enc     = (const float*)d_in[0];
    const float* pooled  = (const float*)d_in[1];
    const int*   traw    = (const int*)d_in[2];
    const float* emb     = (const float*)d_in[3];
    const float* W_enc   = (const float*)d_in[4];
    const float* b_enc   = (const float*)d_in[5];
    const float* W_dec   = (const float*)d_in[6];
    const float* b_dec   = (const float*)d_in[7];
    const float* W_score = (const float*)d_in[8];
    const float* W_ih    = (const float*)d_in[10];
    const float* W_hh    = (const float*)d_in[11];
    const float* b_ih    = (const float*)d_in[12];
    const float* b_hh    = (const float*)d_in[13];
    const float* W_out   = (const float*)d_in[14];
    const float* b_out   = (const float*)d_in[15];
    const float* W_init  = (const float*)d_in[16];
    const float* b_init  = (const float*)d_in[17];
    float* out = (float*)d_out;

    float *p_encproj, *p_hall;
    cudaGetSymbolAddress((void**)&p_encproj, g_enc_proj);
    cudaGetSymbolAddress((void**)&p_hall,    g_h_all);

    reset_bar<<<1, 1>>>();
    detect_tok_dtype<<<1, 256>>>(traw);
    pack_wcat<<<(NG * KX + 255) / 256, 256>>>(W_ih, W_hh);
    pack_bcat<<<(NG + 255) / 256, 256>>>(b_ih, b_hh);

    // enc_proj: M=12544, N=256, K=512
    gemm_tf32<128, 128, 0><<<dim3(An / 128, (Bn * Sn) / 128, 1), 256>>>(
        enc, W_enc, p_encproj, b_enc, Bn * Sn, An, En);

    setup_h0<<<Bn, 256>>>(pooled, W_init, b_init, W_dec, b_dec);

    // whole 31-step recurrence: ONE persistent launch
    recurrent_persistent<<<GP, 256>>>(enc, W_score, traw, emb, W_dec, b_dec);

    // logits: M=1984, N=32000, K=512
    gemm_tf32<128, 128, 2><<<dim3((Tn * Bn + 127) / 128, Vn / 128, 1), 256>>>(
        p_hall, W_out, out, b_out, Tn * Bn, Vn, Hn);
}

// round 10
// speedup vs baseline: 1.5414x; 1.0156x over previous
#include <cuda_runtime.h>
#include <cstdint>

#define DEV_INLINE __device__ __forceinline__

// Problem constants
constexpr int Bn = 64, Sn = 196, En = 512, Hn = 512, An = 256, Dn = 512,
              Vn = 32000, Ln = 32, Tn = 31;
constexpr int KX = 1536;   // xcat row: [embedded(512) | context(512) | h(512)]
constexpr int NG = 2048;   // GRU gemm N: [r(512) z(512) gi_n(512) gh_n(512)]
constexpr int NSPL = 8;    // split-K factor inside persistent kernel
constexpr int SCH = 16;                      // score rows per chunk
constexpr int NCH = (Sn + SCH - 1) / SCH;    // 13 chunks
constexpr int GP = 128;    // persistent grid (single wave guaranteed: <148 SMs)

// Scratch (device globals). 16B-aligned.
__device__ __align__(16) float g_enc_proj[Bn * Sn * An];
__device__ __align__(16) float g_h_all[2048 * Hn];      // PRE-ROUNDED tf32 bits
__device__ __align__(16) float g_xcat[Bn * KX];         // PRE-ROUNDED tf32 bits
__device__ __align__(16) float g_gpart[NSPL * Bn * NG];
__device__ __align__(16) float g_hbuf[2][Bn * Hn];      // full fp32 h
__device__ __align__(16) float g_decproj[Bn * An];
__device__ __align__(16) float g_Wcat[NG * KX];         // PRE-ROUNDED tf32 bits
__device__ __align__(16) float g_bcat[NG];
__device__ __align__(16) float g_scores[Bn * Sn];
__device__ __align__(16) float g_Wout_r[Vn * Hn];       // PRE-ROUNDED W_out (65MB)
__device__ int g_tok_is_i64;
__device__ int g_bar_cnt;
__device__ int g_bar_sense;

DEV_INLINE float tanh_fast(float x) {
    float y; asm("tanh.approx.f32 %0, %1;" : "=f"(y) : "f"(x)); return y;
}
// RNA tf32 rounding: fp32 bits with low 13 mantissa bits zeroed (RZ-safe).
DEV_INLINE unsigned f2tf32(float f) {
    unsigned u; asm("cvt.rna.tf32.f32 %0, %1;" : "=r"(u) : "f"(f)); return u;
}
DEV_INLINE float roundtf(float f) { return __uint_as_float(f2tf32(f)); }
DEV_INLINE unsigned fau(float f) { return __float_as_uint(f); }
DEV_INLINE void mma8(float c[4], const unsigned a[4], const unsigned b[2]) {
    asm volatile(
        "mma.sync.aligned.m16n8k8.row.col.f32.tf32.tf32.f32 "
        "{%0,%1,%2,%3}, {%4,%5,%6,%7}, {%8,%9}, {%0,%1,%2,%3};"
        : "+f"(c[0]), "+f"(c[1]), "+f"(c[2]), "+f"(c[3])
        : "r"(a[0]), "r"(a[1]), "r"(a[2]), "r"(a[3]), "r"(b[0]), "r"(b[1]));
}
DEV_INLINE void cp_async16(void* smem_dst, const void* gsrc) {
    unsigned dst = (unsigned)__cvta_generic_to_shared(smem_dst);
    asm volatile("cp.async.ca.shared.global [%0], [%1], 16;" :: "r"(dst), "l"(gsrc));
}

// ---------------------------------------------------------------------------
__global__ void reset_bar() { g_bar_cnt = 0; g_bar_sense = 0; }

__global__ void detect_tok_dtype(const int* __restrict__ traw)
{
    __shared__ int any;
    if (threadIdx.x == 0) any = 0;
    __syncthreads();
    for (int i = threadIdx.x; i < (Bn * Ln) / 2; i += blockDim.x)
        if (traw[2 * i + 1] != 0) any = 1;
    __syncthreads();
    if (threadIdx.x == 0) g_tok_is_i64 = (any == 0) ? 1 : 0;
}

// Pre-round W_out into g_Wout_r (vectorized grid-stride)
__global__ void round_wout(const float* __restrict__ W)
{
    const float4* src = reinterpret_cast<const float4*>(W);
    float4* dst = reinterpret_cast<float4*>(g_Wout_r);
    const int n = (Vn * Hn) / 4;
    for (int i = blockIdx.x * blockDim.x + threadIdx.x; i < n;
         i += gridDim.x * blockDim.x) {
        float4 v = src[i];
        v.x = roundtf(v.x); v.y = roundtf(v.y);
        v.z = roundtf(v.z); v.w = roundtf(v.w);
        dst[i] = v;
    }
}

// ---------------------------------------------------------------------------
// Standalone tf32 GEMM. PRER=true: operands pre-rounded, feed raw bits.
// MODE 0: C = acc + bias (row-major), guard m<M
// MODE 2: logits: row m -> (t=m/64, b=m%64): out[(b*31+t)*N + n] + bias
// ---------------------------------------------------------------------------
template <int BM, int BN, int MODE, bool PRER>
__global__ __launch_bounds__(256) void gemm_tf32(
    const float* __restrict__ A, const float* __restrict__ B,
    float* __restrict__ C, const float* __restrict__ bias,
    int M, int N, int K)
{
    constexpr int BK = 16;
    constexpr int LDS_ = BK + 4;
    __shared__ float As[2][BM][LDS_];
    __shared__ float Bs[2][BN][LDS_];

    const int tid = threadIdx.x;
    const int lane = tid & 31;
    const int wid = tid >> 5;
    const int grp = lane >> 2;
    const int tig = lane & 3;

    constexpr int NWN = 4;
    const int wm = wid / NWN;
    const int wn = wid % NWN;
    constexpr int WTM = BM / 2;
    constexpr int WTN = BN / 4;
    constexpr int MI = WTM / 16;
    constexpr int NI = WTN / 8;

    int mblk, nblk;
    if (MODE == 2) { mblk = blockIdx.x; nblk = blockIdx.y; }
    else           { mblk = blockIdx.y; nblk = blockIdx.x; }

    const int kIters = K / BK;
    const int lr = tid >> 2;
    const int lc = (tid & 3) * 4;
    constexpr int LA = BM / 64;
    constexpr int LB = BN / 64;

    auto cv = [](float v) -> unsigned {
        if constexpr (PRER) return __float_as_uint(v);
        else { unsigned u; asm("cvt.rna.tf32.f32 %0, %1;" : "=r"(u) : "f"(v)); return u; }
    };

    auto issueTile = [&](int kt, int st) {
        const int kg = kt * BK + lc;
#pragma unroll
        for (int i = 0; i < LA; i++) {
            int gr = mblk * BM + lr + i * 64;
            if (gr >= M) gr = M - 1;
            cp_async16(&As[st][lr + i * 64][lc], A + (size_t)gr * K + kg);
        }
#pragma unroll
        for (int i = 0; i < LB; i++) {
            int gr = nblk * BN + lr + i * 64;
            cp_async16(&Bs[st][lr + i * 64][lc], B + (size_t)gr * K + kg);
        }
        asm volatile("cp.async.commit_group;");
    };

    float acc[MI][NI][4];
#pragma unroll
    for (int mi = 0; mi < MI; mi++)
#pragma unroll
        for (int ni = 0; ni < NI; ni++)
#pragma unroll
            for (int q = 0; q < 4; q++) acc[mi][ni][q] = 0.f;

    issueTile(0, 0);
    for (int kt = 0; kt < kIters; kt++) {
        asm volatile("cp.async.wait_group 0;" ::: "memory");
        __syncthreads();
        if (kt + 1 < kIters) issueTile(kt + 1, (kt + 1) & 1);
        const int st = kt & 1;

#pragma unroll
        for (int ks = 0; ks < 2; ks++) {
            const int k0 = ks * 8;
            unsigned af[MI][4];
#pragma unroll
            for (int mi = 0; mi < MI; mi++) {
                const int r = wm * WTM + mi * 16 + grp;
                af[mi][0] = cv(As[st][r][k0 + tig]);
                af[mi][1] = cv(As[st][r + 8][k0 + tig]);
                af[mi][2] = cv(As[st][r][k0 + tig + 4]);
                af[mi][3] = cv(As[st][r + 8][k0 + tig + 4]);
            }
            unsigned bf[NI][2];
#pragma unroll
            for (int ni = 0; ni < NI; ni++) {
                const int c = wn * WTN + ni * 8 + grp;
                bf[ni][0] = cv(Bs[st][c][k0 + tig]);
                bf[ni][1] = cv(Bs[st][c][k0 + tig + 4]);
            }
#pragma unroll
            for (int mi = 0; mi < MI; mi++)
#pragma unroll
                for (int ni = 0; ni < NI; ni++)
                    mma8(acc[mi][ni], af[mi], bf[ni]);
        }
        __syncthreads();
    }

#pragma unroll
    for (int mi = 0; mi < MI; mi++) {
#pragma unroll
        for (int ni = 0; ni < NI; ni++) {
            const int r0 = mblk * BM + wm * WTM + mi * 16 + grp;
            const int c0 = nblk * BN + wn * WTN + ni * 8 + tig * 2;
#pragma unroll
            for (int hh = 0; hh < 2; hh++) {
                const int r = r0 + hh * 8;
                const float v0 = acc[mi][ni][hh * 2 + 0];
                const float v1 = acc[mi][ni][hh * 2 + 1];
                if (MODE == 0) {
                    if (r < M) {
                        C[(size_t)r * N + c0]     = v0 + bias[c0];
                        C[(size_t)r * N + c0 + 1] = v1 + bias[c0 + 1];
                    }
                } else {
                    if (r < M) {
                        const int tt = r >> 6, bb = r & 63;
                        const size_t o = ((size_t)bb * Tn + tt) * (size_t)N + c0;
                        C[o]     = v0 + bias[c0];
                        C[o + 1] = v1 + bias[c0 + 1];
                    }
                }
            }
        }
    }
}

// ---------------------------------------------------------------------------
// Weight packing (idempotent each launch); stores PRE-ROUNDED tf32 bits.
// ---------------------------------------------------------------------------
__global__ void pack_wcat(const float* __restrict__ W_ih,
                          const float* __restrict__ W_hh)
{
    const int idx = blockIdx.x * blockDim.x + threadIdx.x;
    if (idx >= NG * KX) return;
    const int j = idx / KX, k = idx - j * KX;
    float v = 0.f;
    if (j < 1536) {
        if (k < 1024) v = W_ih[(size_t)j * 1024 + k];
        else if (j < 1024) v = W_hh[(size_t)j * 512 + (k - 1024)];
    } else {
        if (k >= 1024) v = W_hh[(size_t)(j - 512) * 512 + (k - 1024)];
    }
    g_Wcat[idx] = roundtf(v);
}

__global__ void pack_bcat(const float* __restrict__ b_ih,
                          const float* __restrict__ b_hh)
{
    const int j = blockIdx.x * blockDim.x + threadIdx.x;
    if (j >= NG) return;
    float v;
    if (j < 1024)      v = b_ih[j] + b_hh[j];
    else if (j < 1536) v = b_ih[j];
    else               v = b_hh[j - 512];
    g_bcat[j] = v;
}

// ---------------------------------------------------------------------------
// Setup: h0 = tanh(pooled @ W_init.T + b_init); dec_proj(h0) + b_dec
// ---------------------------------------------------------------------------
__global__ void setup_h0(const float* __restrict__ pooled,
                         const float* __restrict__ W_init,
                         const float* __restrict__ b_init,
                         const float* __restrict__ W_dec,
                         const float* __restrict__ b_dec)
{
    __shared__ float h0s[Hn];
    const int b = blockIdx.x;
    const int tid = threadIdx.x, wid = tid >> 5, lane = tid & 31;
    const float* pb = pooled + (size_t)b * En;

    for (int j = wid; j < Hn; j += 8) {
        const float* wr = W_init + (size_t)j * En;
        float s = 0.f;
        for (int e = lane; e < En; e += 32) s += pb[e] * wr[e];
#pragma unroll
        for (int o = 16; o > 0; o >>= 1) s += __shfl_xor_sync(0xffffffffu, s, o);
        if (lane == 0) h0s[j] = tanhf(s + b_init[j]);
    }
    __syncthreads();
    for (int j = tid; j < Hn; j += blockDim.x) {
        const float v = h0s[j];
        g_hbuf[0][b * Hn + j] = v;
        g_xcat[b * KX + 1024 + j] = roundtf(v);
    }
    for (int a = wid; a < An; a += 8) {
        const float* wr = W_dec + (size_t)a * Hn;
        float s = 0.f;
        for (int e = lane; e < Hn; e += 32) s += h0s[e] * wr[e];
#pragma unroll
        for (int o = 16; o > 0; o >>= 1) s += __shfl_xor_sync(0xffffffffu, s, o);
        if (lane == 0) g_decproj[b * An + a] = s + b_dec[a];
    }
}

// ---------------------------------------------------------------------------
// Persistent recurrent kernel: all Tn steps, 4 grid barriers per step.
// ---------------------------------------------------------------------------
__global__ __launch_bounds__(256) void recurrent_persistent(
    const float* __restrict__ enc, const float* __restrict__ W_score,
    const int* __restrict__ traw, const float* __restrict__ emb,
    const float* __restrict__ W_dec, const float* __restrict__ b_dec)
{
    __shared__ float As3[2][64][20];
    __shared__ float Bs3[2][128][20];
    __shared__ float dp[An];
    __shared__ float w[256];
    __shared__ float hs[Hn];
    __shared__ float red[8];
    __shared__ int sSense;

    const int tid = threadIdx.x;
    const int lane = tid & 31;
    const int wid = tid >> 5;
    const int grp = lane >> 2;
    const int tig = lane & 3;

    if (tid == 0) sSense = 0;
    __syncthreads();

    auto gbar = [&]() {
        __syncthreads();
        if (tid == 0) {
            __threadfence();
            const int target = sSense ^ 1;
            if (atomicAdd(&g_bar_cnt, 1) == GP - 1) {
                g_bar_cnt = 0;
                __threadfence();
                atomicExch(&g_bar_sense, target);
            } else {
                while (*(volatile int*)&g_bar_sense != target) { }
            }
            __threadfence();
            sSense = target;
        }
        __syncthreads();
    };

    for (int t = 0; t < Tn; t++) {
        const int par = t & 1;

        // ---- Phase 1: scores ----
        for (int u = blockIdx.x; u < Bn * NCH; u += GP) {
            const int b = u / NCH, ch = u - b * NCH;
            dp[tid] = g_decproj[b * An + tid];
            __syncthreads();
            const int sLo = ch * SCH, sHi = min(sLo + SCH, Sn);
            for (int s = sLo + wid; s < sHi; s += 8) {
                const float* er = g_enc_proj + ((size_t)b * Sn + s) * An;
                float sc = 0.f;
#pragma unroll
                for (int a = lane; a < An; a += 32)
                    sc += tanh_fast(er[a] + dp[a]) * W_score[a];
#pragma unroll
                for (int o = 16; o > 0; o >>= 1)
                    sc += __shfl_xor_sync(0xffffffffu, sc, o);
                if (lane == 0) g_scores[b * Sn + s] = sc;
            }
            __syncthreads();
        }
        gbar();

        // ---- Phase 2: softmax + context + embed (2 CTAs per batch) ----
        {
            const int u = blockIdx.x;
            const int b = u >> 1, half = u & 1;

            if (half == 0) {
                const int i = b * Ln + t;
                int tok = g_tok_is_i64 ? traw[2 * i] : traw[i];
                if (tok < 0) tok = 0;
                if (tok >= Vn) tok = Vn - 1;
                const float* er = emb + (size_t)tok * Dn;
                const bool pad = (tok == 2);
                for (int d = tid; d < Dn; d += 256)
                    g_xcat[b * KX + d] = pad ? 0.f : roundtf(er[d]);
            }

            const float v = (tid < Sn) ? g_scores[b * Sn + tid] : -1e30f;
            float mx = v;
#pragma unroll
            for (int o = 16; o > 0; o >>= 1)
                mx = fmaxf(mx, __shfl_xor_sync(0xffffffffu, mx, o));
            if (lane == 0) red[wid] = mx;
            __syncthreads();
            float gmx = red[0];
#pragma unroll
            for (int i = 1; i < 8; i++) gmx = fmaxf(gmx, red[i]);
            __syncthreads();
            const float ev = (tid < Sn) ? __expf(v - gmx) : 0.f;
            float sm = ev;
#pragma unroll
            for (int o = 16; o > 0; o >>= 1)
                sm += __shfl_xor_sync(0xffffffffu, sm, o);
            if (lane == 0) red[wid] = sm;
            __syncthreads();
            float tot = 0.f;
#pragma unroll
            for (int i = 0; i < 8; i++) tot += red[i];
            if (tid < Sn) w[tid] = ev * (1.f / tot);
            __syncthreads();

            const int e0 = half * 256 + tid;
            const float* eb = enc + (size_t)b * Sn * En;
            float acc = 0.f;
#pragma unroll 4
            for (int s = 0; s < Sn; s++) acc += w[s] * eb[(size_t)s * En + e0];
            g_xcat[b * KX + 512 + e0] = roundtf(acc);
            __syncthreads();
        }
        gbar();

        // ---- Phase 3: GRU gates GEMM (pre-rounded operands, raw bits) ----
        {
            const int u = blockIdx.x;
            const int nblk = u >> 3, split = u & 7;
            const int kbase = split * (KX / NSPL);
            constexpr int kIters = (KX / NSPL) / 16;
            const int wm = wid >> 2, wn = wid & 3;
            const int lr = tid >> 2, lc = (tid & 3) * 4;

            auto issue3 = [&](int kt, int st) {
                const int kg = kbase + kt * 16 + lc;
                cp_async16(&As3[st][lr][lc], g_xcat + (size_t)lr * KX + kg);
                cp_async16(&Bs3[st][lr][lc],
                           g_Wcat + (size_t)(nblk * 128 + lr) * KX + kg);
                cp_async16(&Bs3[st][lr + 64][lc],
                           g_Wcat + (size_t)(nblk * 128 + lr + 64) * KX + kg);
                asm volatile("cp.async.commit_group;");
            };

            float acc[2][4][4];
#pragma unroll
            for (int mi = 0; mi < 2; mi++)
#pragma unroll
                for (int ni = 0; ni < 4; ni++)
#pragma unroll
                    for (int q = 0; q < 4; q++) acc[mi][ni][q] = 0.f;

            issue3(0, 0);
            for (int kt = 0; kt < kIters; kt++) {
                asm volatile("cp.async.wait_group 0;" ::: "memory");
                __syncthreads();
                if (kt + 1 < kIters) issue3(kt + 1, (kt + 1) & 1);
                const int st = kt & 1;
#pragma unroll
                for (int ks = 0; ks < 2; ks++) {
                    const int k0 = ks * 8;
                    unsigned af[2][4];
#pragma unroll
                    for (int mi = 0; mi < 2; mi++) {
                        const int r = wm * 32 + mi * 16 + grp;
                        af[mi][0] = fau(As3[st][r][k0 + tig]);
                        af[mi][1] = fau(As3[st][r + 8][k0 + tig]);
                        af[mi][2] = fau(As3[st][r][k0 + tig + 4]);
                        af[mi][3] = fau(As3[st][r + 8][k0 + tig + 4]);
                    }
                    unsigned bf[4][2];
#pragma unroll
                    for (int ni = 0; ni < 4; ni++) {
                        const int c = wn * 32 + ni * 8 + grp;
                        bf[ni][0] = fau(Bs3[st][c][k0 + tig]);
                        bf[ni][1] = fau(Bs3[st][c][k0 + tig + 4]);
                    }
#pragma unroll
                    for (int mi = 0; mi < 2; mi++)
#pragma unroll
                        for (int ni = 0; ni < 4; ni++)
                            mma8(acc[mi][ni], af[mi], bf[ni]);
                }
                __syncthreads();
            }

            float* gp = g_gpart + (size_t)split * Bn * NG;
#pragma unroll
            for (int mi = 0; mi < 2; mi++)
#pragma unroll
                for (int ni = 0; ni < 4; ni++) {
                    const int r0 = wm * 32 + mi * 16 + grp;
                    const int c0 = nblk * 128 + wn * 32 + ni * 8 + tig * 2;
#pragma unroll
                    for (int hh = 0; hh < 2; hh++) {
                        const int r = r0 + hh * 8;
                        gp[(size_t)r * NG + c0]     = acc[mi][ni][hh * 2 + 0];
                        gp[(size_t)r * NG + c0 + 1] = acc[mi][ni][hh * 2 + 1];
                    }
                }
        }
        gbar();

        // ---- Phase 4: gates + decproj ----
        {
            const int u = blockIdx.x;
            const int b = u >> 1, ah = u & 1;
#pragma unroll
            for (int jj = 0; jj < 2; jj++) {
                const int j = tid + jj * 256;
                float rp  = g_bcat[j];
                float zp  = g_bcat[512 + j];
                float gin = g_bcat[1024 + j];
                float ghn = g_bcat[1536 + j];
#pragma unroll
                for (int p = 0; p < NSPL; p++) {
                    const float* gp = g_gpart + ((size_t)p * Bn + b) * NG;
                    rp  += gp[j];
                    zp  += gp[512 + j];
                    gin += gp[1024 + j];
                    ghn += gp[1536 + j];
                }
                const float r = 1.f / (1.f + expf(-rp));
                const float z = 1.f / (1.f + expf(-zp));
                const float n = tanhf(gin + r * ghn);
                const float hprev = g_hbuf[par][b * Hn + j];
                const float hn = (1.f - z) * n + z * hprev;
                hs[j] = hn;
                if (ah == 0) {
                    g_hbuf[par ^ 1][b * Hn + j] = hn;
                    const float hr = roundtf(hn);
                    g_xcat[b * KX + 1024 + j] = hr;
                    g_h_all[((size_t)t * Bn + b) * Hn + j] = hr;
                }
            }
            __syncthreads();

            for (int a = ah * 128 + wid; a < ah * 128 + 128; a += 8) {
                const float* wr = W_dec + (size_t)a * Hn;
                float s = 0.f;
                for (int e = lane; e < Hn; e += 32) s += hs[e] * wr[e];
#pragma unroll
                for (int o = 16; o > 0; o >>= 1)
                    s += __shfl_xor_sync(0xffffffffu, s, o);
                if (lane == 0) g_decproj[b * An + a] = s + b_dec[a];
            }
            __syncthreads();
        }
        gbar();
    }
}

// ---------------------------------------------------------------------------
extern "C" void kernel_launch(void* const* d_in, const int* in_sizes, int n_in,
                              void* d_out, int out_size)
{
    (void)in_sizes; (void)n_in; (void)out_size;
    const float* enc     = (const float*)d_in[0];
    const float* pooled  = (const float*)d_in[1];
    const int*   traw    = (const int*)d_in[2];
    const float* emb     = (const float*)d_in[3];
    const float* W_enc   = (const float*)d_in[4];
    const float* b_enc   = (const float*)d_in[5];
    const float* W_dec   = (const float*)d_in[6];
    const float* b_dec   = (const float*)d_in[7];
    const float* W_score = (const float*)d_in[8];
    const float* W_ih    = (const float*)d_in[10];
    const float* W_hh    = (const float*)d_in[11];
    const float* b_ih    = (const float*)d_in[12];
    const float* b_hh    = (const float*)d_in[13];
    const float* W_out   = (const float*)d_in[14];
    const float* b_out   = (const float*)d_in[15];
    const float* W_init  = (const float*)d_in[16];
    const float* b_init  = (const float*)d_in[17];
    float* out = (float*)d_out;

    float *p_encproj, *p_hall, *p_woutr;
    cudaGetSymbolAddress((void**)&p_encproj, g_enc_proj);
    cudaGetSymbolAddress((void**)&p_hall,    g_h_all);
    cudaGetSymbolAddress((void**)&p_woutr,   g_Wout_r);

    reset_bar<<<1, 1>>>();
    detect_tok_dtype<<<1, 256>>>(traw);
    pack_wcat<<<(NG * KX + 255) / 256, 256>>>(W_ih, W_hh);
    pack_bcat<<<(NG + 255) / 256, 256>>>(b_ih, b_hh);
    round_wout<<<4096, 256>>>(W_out);

    // enc_proj: M=12544, N=256, K=512 (inputs not pre-rounded -> PRER=false)
    gemm_tf32<128, 128, 0, false><<<dim3(An / 128, (Bn * Sn) / 128, 1), 256>>>(
        enc, W_enc, p_encproj, b_enc, Bn * Sn, An, En);

    setup_h0<<<Bn, 256>>>(pooled, W_init, b_init, W_dec, b_dec);

    // whole 31-step recurrence: ONE persistent launch
    recurrent_persistent<<<GP, 256>>>(enc, W_score, traw, emb, W_dec, b_dec);

    // logits: M=1984, N=32000, K=512 (both operands pre-rounded -> PRER=true)
    gemm_tf32<128, 128, 2, true><<<dim3((Tn * Bn + 127) / 128, Vn / 128, 1), 256>>>(
        p_hall, p_woutr, out, b_out, Tn * Bn, Vn, Hn);
}